// round 10
// baseline (speedup 1.0000x reference)
#include <cuda_runtime.h>
#include <cuda_bf16.h>
#include <stdint.h>

// ---------------------------------------------------------------------------
// VectorQuantizer on GB300 — exact fp32 FFMA2 distance GEMM.
//   z      : [64, 256, 32, 32] f32   (d_in[0])
//   emb_w  : [1024, 256]       f32   (d_in[1])
//   out    : z_q [64,256,32,32] f32, then loss scalar (last element)
//
// d = fl( fl(z_sq + e_sq[k]) - 2*dot_k ), fp32; ties -> lowest code index.
// f32x2 packs ROW pairs (z side); e values are pre-duplicated at pack time so
// the inner loop is pure {LDS.128, FFMA2}. Staging is register-prefetched
// (LDG at phase start, STS at phase end). Static smem only; no cp.async.
// ---------------------------------------------------------------------------

#define CDIM   256
#define NROWS  65536
#define KCODES 1024

__device__ float g_esq[KCODES];
__device__ float g_zsq[NROWS];
__device__ int   g_idx[NROWS];
__device__ float g_partials[2048];
// 128 tiles (tile = kt*8 + c0, kt<16 ktiles of 64 codes, c0<8 c-chunks of 32)
// of 4096 floats: [cc 0..31][chunk 0..31][q 0..1][dup 0..1]; chunk holds
// codes kt*64 + 2*chunk (+q), each value duplicated, for column c0*32+cc.
__device__ __align__(16) float g_epack[128 * 4096];   // 2 MB

// ---------------------------------------------------------------------------
__device__ __forceinline__ unsigned long long ffma2(unsigned long long a,
                                                    unsigned long long b,
                                                    unsigned long long c) {
    unsigned long long d;
    asm("fma.rn.f32x2 %0, %1, %2, %3;" : "=l"(d) : "l"(a), "l"(b), "l"(c));
    return d;
}
__device__ __forceinline__ void unpack2(unsigned long long v, float& lo, float& hi) {
    asm("mov.b64 {%0, %1}, %2;" : "=f"(lo), "=f"(hi) : "l"(v));
}

// ---------------------------------------------------------------------------
// K0: pack emb into duplicated, chunk-interleaved tiles
// ---------------------------------------------------------------------------
__global__ void k_epack(const float* __restrict__ emb) {
    int idx = blockIdx.x * 256 + threadIdx.x;      // 262144 = 1024 * 256
    int k = idx >> 8, c = idx & 255;
    int kt = k >> 6, r = k & 63, chunk = r >> 1, q = r & 1;
    int c0 = c >> 5, cc = c & 31;
    float v = emb[k * CDIM + c];
    float* dst = g_epack + ((size_t)(kt * 8 + c0)) * 4096
                         + cc * 128 + chunk * 4 + q * 2;
    dst[0] = v;
    dst[1] = v;
}

// ---------------------------------------------------------------------------
// K1: norms
// ---------------------------------------------------------------------------
__global__ void k_esq(const float* __restrict__ emb) {
    int w = (blockIdx.x * blockDim.x + threadIdx.x) >> 5, lane = threadIdx.x & 31;
    if (w >= KCODES) return;
    const float* row = emb + (size_t)w * CDIM;
    float s = 0.f;
#pragma unroll
    for (int i = lane; i < CDIM; i += 32) { float v = row[i]; s = fmaf(v, v, s); }
#pragma unroll
    for (int o = 16; o; o >>= 1) s += __shfl_xor_sync(0xffffffffu, s, o);
    if (!lane) g_esq[w] = s;
}
__global__ void k_zsq(const float* __restrict__ z) {
    int n = blockIdx.x * 256 + threadIdx.x;
    int b = n >> 10, hw = n & 1023;
    const float* p = z + (((size_t)b * CDIM) << 10) + hw;
    float s = 0.f;
#pragma unroll 8
    for (int c = 0; c < CDIM; c++) { float v = p[(size_t)c << 10]; s = fmaf(v, v, s); }
    g_zsq[n] = s;
}

// ---------------------------------------------------------------------------
// K2: fused distance GEMM + argmin.
//   block: 128 rows x 1024 codes; 128 flat steps (kt 0..15 x c0 0..7).
//   thread (tx=t&15, ty=t>>4): rows ty*8+0..7 as 4 f32x2 row-pairs;
//   4 codes/ktile: chunks {tx, 16+tx} x {q=0,1}.
//   acc[p][sc*2+q] halves = dots of rows (ty*8+2p, +1) vs code
//   kt*64 + (sc*16+tx)*2 + q.
//   Staging pipeline: LDG next step's tiles into regs at phase start,
//   STS after compute; two barriers/step.
// ---------------------------------------------------------------------------
__global__ void __launch_bounds__(256, 2)
k_dist_argmin(const float* __restrict__ z) {
    __shared__ __align__(16) union {
        struct { float zb[4096]; float eb[4096]; } a;   // 32 KB
        struct { float d[128][16]; int i[128][16]; } b; // 16 KB
    } sm;
    __shared__ float s_esq[KCODES];
    __shared__ float s_zsq[128];

    const int t    = threadIdx.x;
    const int tx   = t & 15;
    const int ty   = t >> 4;
    const int row0 = blockIdx.x * 128;
    const int bb   = row0 >> 10;
    const int hw0  = row0 & 1023;

    for (int i = t; i < KCODES; i += 256) s_esq[i] = g_esq[i];
    if (t < 128) s_zsq[t] = g_zsq[row0 + t];

    const float* zsrc0 = z + (((size_t)bb * CDIM) << 10) + hw0;

    // staging decomposition: 1024 16B-chunks each for z and e, 4/thread.
    // z: id = t + 256*j -> c-row cr = id>>5 (0..31), col co = (id&31)*4.
    // e: linear copy of the 16KB g_epack tile (tile index == step index s).
    const int cr0 = t >> 5;            // cr[j] = cr0 + 8*j
    const int co0 = (t & 31) * 4;      // co[j] = co0
    float4 zr0, zr1, zr2, zr3, er0, er1, er2, er3;

    // prologue: stage step 0
    {
        const float* zs = zsrc0;       // c0 = 0
        zr0 = *reinterpret_cast<const float4*>(zs + (((size_t)(cr0 +  0)) << 10) + co0);
        zr1 = *reinterpret_cast<const float4*>(zs + (((size_t)(cr0 +  8)) << 10) + co0);
        zr2 = *reinterpret_cast<const float4*>(zs + (((size_t)(cr0 + 16)) << 10) + co0);
        zr3 = *reinterpret_cast<const float4*>(zs + (((size_t)(cr0 + 24)) << 10) + co0);
        const float4* es = reinterpret_cast<const float4*>(g_epack) + t * 4;
        er0 = es[0]; er1 = es[1]; er2 = es[2]; er3 = es[3];
        *reinterpret_cast<float4*>(&sm.a.zb[(cr0 +  0) * 128 + co0]) = zr0;
        *reinterpret_cast<float4*>(&sm.a.zb[(cr0 +  8) * 128 + co0]) = zr1;
        *reinterpret_cast<float4*>(&sm.a.zb[(cr0 + 16) * 128 + co0]) = zr2;
        *reinterpret_cast<float4*>(&sm.a.zb[(cr0 + 24) * 128 + co0]) = zr3;
        *reinterpret_cast<float4*>(&sm.a.eb[t * 16 +  0]) = er0;
        *reinterpret_cast<float4*>(&sm.a.eb[t * 16 +  4]) = er1;
        *reinterpret_cast<float4*>(&sm.a.eb[t * 16 +  8]) = er2;
        *reinterpret_cast<float4*>(&sm.a.eb[t * 16 + 12]) = er3;
    }

    float bestD[8];
    int   bestI[8];
#pragma unroll
    for (int i = 0; i < 8; ++i) { bestD[i] = __int_as_float(0x7f800000); bestI[i] = 0; }

    unsigned long long acc[4][4];

    for (int s = 0; s < 128; s++) {
        __syncthreads();                 // staged tiles for step s visible

        if (s < 127) {                   // prefetch step s+1 (overlaps compute)
            const int c0n = (s + 1) & 7;
            const float* zs = zsrc0 + (((size_t)(c0n * 32)) << 10);
            zr0 = *reinterpret_cast<const float4*>(zs + (((size_t)(cr0 +  0)) << 10) + co0);
            zr1 = *reinterpret_cast<const float4*>(zs + (((size_t)(cr0 +  8)) << 10) + co0);
            zr2 = *reinterpret_cast<const float4*>(zs + (((size_t)(cr0 + 16)) << 10) + co0);
            zr3 = *reinterpret_cast<const float4*>(zs + (((size_t)(cr0 + 24)) << 10) + co0);
            const float4* es = reinterpret_cast<const float4*>(
                g_epack + ((size_t)(s + 1)) * 4096) + t * 4;
            er0 = es[0]; er1 = es[1]; er2 = es[2]; er3 = es[3];
        }

        if ((s & 7) == 0) {
#pragma unroll
            for (int p = 0; p < 4; ++p)
#pragma unroll
                for (int j = 0; j < 4; ++j) acc[p][j] = 0ull;
        }

#pragma unroll 4
        for (int cc = 0; cc < 32; cc++) {
            ulonglong2 zp = *reinterpret_cast<const ulonglong2*>(
                &sm.a.zb[cc * 128 + ty * 8]);
            ulonglong2 zq = *reinterpret_cast<const ulonglong2*>(
                &sm.a.zb[cc * 128 + ty * 8 + 4]);
            unsigned long long zrp[4] = { zp.x, zp.y, zq.x, zq.y };
#pragma unroll
            for (int sc = 0; sc < 2; sc++) {
                ulonglong2 ep = *reinterpret_cast<const ulonglong2*>(
                    &sm.a.eb[cc * 128 + (sc * 16 + tx) * 4]);
#pragma unroll
                for (int p = 0; p < 4; p++) {
                    acc[p][sc * 2 + 0] = ffma2(zrp[p], ep.x, acc[p][sc * 2 + 0]);
                    acc[p][sc * 2 + 1] = ffma2(zrp[p], ep.y, acc[p][sc * 2 + 1]);
                }
            }
        }

        if ((s & 7) == 7) {
            // ktile epilogue: per-thread codes ascend (sc, q); strict < = first-min
            const int kb = (s >> 3) * 64;
#pragma unroll
            for (int p = 0; p < 4; p++) {
                float zq0 = s_zsq[ty * 8 + 2 * p];
                float zq1 = s_zsq[ty * 8 + 2 * p + 1];
#pragma unroll
                for (int sc = 0; sc < 2; sc++) {
#pragma unroll
                    for (int q = 0; q < 2; q++) {
                        int   k   = kb + (sc * 16 + tx) * 2 + q;
                        float esq = s_esq[k];
                        float lo, hi;
                        unpack2(acc[p][sc * 2 + q], lo, hi);
                        float d0 = fmaf(-2.0f, lo, zq0 + esq);
                        if (d0 < bestD[2 * p]) { bestD[2 * p] = d0; bestI[2 * p] = k; }
                        float d1 = fmaf(-2.0f, hi, zq1 + esq);
                        if (d1 < bestD[2 * p + 1]) { bestD[2 * p + 1] = d1; bestI[2 * p + 1] = k; }
                    }
                }
            }
        }

        __syncthreads();                 // all reads of step s done
        if (s < 127) {                   // write step s+1 tiles
            *reinterpret_cast<float4*>(&sm.a.zb[(cr0 +  0) * 128 + co0]) = zr0;
            *reinterpret_cast<float4*>(&sm.a.zb[(cr0 +  8) * 128 + co0]) = zr1;
            *reinterpret_cast<float4*>(&sm.a.zb[(cr0 + 16) * 128 + co0]) = zr2;
            *reinterpret_cast<float4*>(&sm.a.zb[(cr0 + 24) * 128 + co0]) = zr3;
            *reinterpret_cast<float4*>(&sm.a.eb[t * 16 +  0]) = er0;
            *reinterpret_cast<float4*>(&sm.a.eb[t * 16 +  4]) = er1;
            *reinterpret_cast<float4*>(&sm.a.eb[t * 16 +  8]) = er2;
            *reinterpret_cast<float4*>(&sm.a.eb[t * 16 + 12]) = er3;
        }
    }

    // cross-thread (tx) reduction per row, lowest-index tie-break
#pragma unroll
    for (int i = 0; i < 8; ++i) {
        sm.b.d[ty * 8 + i][tx] = bestD[i];
        sm.b.i[ty * 8 + i][tx] = bestI[i];
    }
    __syncthreads();
    if (t < 128) {
        float bd = sm.b.d[t][0];
        int   bi = sm.b.i[t][0];
#pragma unroll
        for (int x = 1; x < 16; ++x) {
            float dd = sm.b.d[t][x];
            int   ii = sm.b.i[t][x];
            if (dd < bd || (dd == bd && ii < bi)) { bd = dd; bi = ii; }
        }
        g_idx[row0 + t] = bi;
    }
}

// ---------------------------------------------------------------------------
// K3: gather z_q -> out ([B,C,H,W]), per-block loss partials
// ---------------------------------------------------------------------------
__global__ void __launch_bounds__(256)
k_output(const float* __restrict__ z, const float* __restrict__ emb,
         float* __restrict__ out) {
    __shared__ float es[32][257];
    __shared__ int   sid[32];
    __shared__ float red[256];

    const int t  = threadIdx.x;
    const int n0 = blockIdx.x * 32;
    if (t < 32) sid[t] = g_idx[n0 + t];
    __syncthreads();

    const int w = t >> 5, lane = t & 31;
#pragma unroll
    for (int r = w * 4; r < w * 4 + 4; ++r) {
        const float* src = emb + (size_t)sid[r] * CDIM;
#pragma unroll
        for (int i = 0; i < CDIM; i += 32) es[r][i + lane] = src[i + lane];
    }
    __syncthreads();

    const int b = n0 >> 10, hwb = n0 & 1023;
    float acc = 0.f;
#pragma unroll 4
    for (int p = 0; p < 32; ++p) {
        int c = p * 8 + (t >> 5);
        int r = t & 31;
        size_t g = (((size_t)(b * CDIM + c)) << 10) + hwb + r;
        float v  = es[r][c];
        float zv = z[g];
        out[g] = v;
        float df = v - zv;
        acc = fmaf(df, df, acc);
    }
    red[t] = acc;
    __syncthreads();
#pragma unroll
    for (int s = 128; s; s >>= 1) {
        if (t < s) red[t] += red[t + s];
        __syncthreads();
    }
    if (!t) g_partials[blockIdx.x] = red[0];
}

// K4: final loss = (1 + BETA) * mean((z_q - z)^2)
__global__ void k_loss(float* __restrict__ lossOut) {
    __shared__ float red[256];
    const int t = threadIdx.x;
    float s = 0.f;
    for (int i = t; i < 2048; i += 256) s += g_partials[i];
    red[t] = s;
    __syncthreads();
#pragma unroll
    for (int st = 128; st; st >>= 1) {
        if (t < st) red[t] += red[t + st];
        __syncthreads();
    }
    if (!t) {
        float m = red[0] * (1.0f / 16777216.0f);
        lossOut[0] = m + 0.25f * m;
    }
}

// ---------------------------------------------------------------------------
extern "C" void kernel_launch(void* const* d_in, const int* in_sizes, int n_in,
                              void* d_out, int out_size) {
    const float* z   = (const float*)d_in[0];
    const float* emb = (const float*)d_in[1];
    float* out       = (float*)d_out;

    k_epack<<<1024, 256>>>(emb);
    k_esq<<<(KCODES * 32) / 256, 256>>>(emb);
    k_zsq<<<NROWS / 256, 256>>>(z);
    k_dist_argmin<<<NROWS / 128, 256>>>(z);
    k_output<<<NROWS / 32, 256>>>(z, emb, out);
    k_loss<<<1, 256>>>(out + (size_t)out_size - 1);
}

// round 15
// speedup vs baseline: 1.5758x; 1.5758x over previous
#include <cuda_runtime.h>
#include <cuda_bf16.h>
#include <stdint.h>

// ---------------------------------------------------------------------------
// VectorQuantizer on GB300 — exact fp32 FFMA2 distance GEMM (round-4 base +
// dense e-operand reads). Resubmission of round-11/14 (infra flake).
//   z      : [64, 256, 32, 32] f32   (d_in[0])
//   emb_w  : [1024, 256]       f32   (d_in[1])
//   out    : z_q [64,256,32,32] f32, then loss scalar (last element)
//
// d = fl( fl(z_sq + e_sq[k]) - 2*dot_k ), fp32; ties -> lowest code index.
// ---------------------------------------------------------------------------

#define CDIM   256
#define NROWS  65536
#define KCODES 1024

__device__ float              g_esq[KCODES];
__device__ float              g_zsq[NROWS];
__device__ int                g_idx[NROWS];
__device__ float              g_partials[2048];
// e packed per (ktile of 128 codes, c-chunk of 32): per cc, 64 u64 slots;
// slot p holds the code pair (e[kb+2p][c], e[kb+2p+1][c]).
__device__ unsigned long long g_epack[131072];   // 1 MB

// ---------------------------------------------------------------------------
__device__ __forceinline__ unsigned long long ffma2(unsigned long long a,
                                                    unsigned long long b,
                                                    unsigned long long c) {
    unsigned long long d;
    asm("fma.rn.f32x2 %0, %1, %2, %3;" : "=l"(d) : "l"(a), "l"(b), "l"(c));
    return d;
}
__device__ __forceinline__ unsigned long long dup2(float z) {
    unsigned long long d;
    asm("mov.b64 %0, {%1, %1};" : "=l"(d) : "f"(z));
    return d;
}
__device__ __forceinline__ void unpack2(unsigned long long v, float& lo, float& hi) {
    asm("mov.b64 {%0, %1}, %2;" : "=f"(lo), "=f"(hi) : "l"(v));
}

// ---------------------------------------------------------------------------
// K0: pack emb into pair-interleaved GEMM tiles (slot = pair identity)
// ---------------------------------------------------------------------------
__global__ void k_epack(const float* __restrict__ emb) {
    int idx = blockIdx.x * 256 + threadIdx.x;     // 262144
    int k = idx & 1023, c = idx >> 10;
    int fidx = (((k >> 7) * 8 + (c >> 5)) * 32 + (c & 31)) * 128 + (k & 127);
    ((float*)g_epack)[fidx] = emb[k * CDIM + c];
}

// ---------------------------------------------------------------------------
// K1: norms
// ---------------------------------------------------------------------------
__global__ void k_esq(const float* __restrict__ emb) {
    int w = (blockIdx.x * blockDim.x + threadIdx.x) >> 5, lane = threadIdx.x & 31;
    if (w >= KCODES) return;
    const float* row = emb + (size_t)w * CDIM;
    float s = 0.f;
#pragma unroll
    for (int i = lane; i < CDIM; i += 32) { float v = row[i]; s = fmaf(v, v, s); }
#pragma unroll
    for (int o = 16; o; o >>= 1) s += __shfl_xor_sync(0xffffffffu, s, o);
    if (!lane) g_esq[w] = s;
}

__global__ void k_zsq(const float* __restrict__ z) {
    int n = blockIdx.x * 256 + threadIdx.x;
    int b = n >> 10, hw = n & 1023;
    const float* p = z + (((size_t)b * CDIM) << 10) + hw;
    float s = 0.f;
#pragma unroll 8
    for (int c = 0; c < CDIM; c++) { float v = p[(size_t)c << 10]; s = fmaf(v, v, s); }
    g_zsq[n] = s;
}

// ---------------------------------------------------------------------------
// K2: fused distance GEMM + argmin, occupancy 2 blocks/SM.
//   block: 128 rows x 1024 codes (8 code-tiles of 128); c chunks of 32.
//   thread (tx=t&15, ty=t>>4): rows ty*8+i (i<8);
//   code pairs {2tx, 2tx+1, 32+2tx, 32+2tx+1}.
//   acc[i][j] is f32x2 over pair j's two codes; z scalar dup'd via mov.b64.
//   e reads are DENSE (16B thread stride): ea at es[cc*64 + 2tx] (2 wf),
//   eb at es[cc*64 + 32 + 2tx] (2 wf).
// ---------------------------------------------------------------------------
__global__ void __launch_bounds__(256, 2)
k_dist_argmin(const float* __restrict__ z) {
    __shared__ __align__(16) union {
        struct { float zsT[32 * 132]; unsigned long long es[2048]; } a;
        struct { float d[128][16]; int i[128][16]; } b;
    } sm;
    __shared__ float s_esq[KCODES];
    __shared__ float s_zsq[128];

    const int t    = threadIdx.x;
    const int tx   = t & 15;
    const int ty   = t >> 4;
    const int row0 = blockIdx.x * 128;
    const int bb   = row0 >> 10;
    const int hw0  = row0 & 1023;

    for (int i = t; i < KCODES; i += 256) s_esq[i] = g_esq[i];
    if (t < 128) s_zsq[t] = g_zsq[row0 + t];

    float bestD[8];
    int   bestI[8];
#pragma unroll
    for (int i = 0; i < 8; ++i) { bestD[i] = __int_as_float(0x7f800000); bestI[i] = 0; }

    const int zr  = t >> 3;             // c-row 0..31
    const int zf4 = (t & 7) * 4;        // float offset within 128-row span

    for (int kt = 0; kt < 8; kt++) {
        unsigned long long acc[8][4];
#pragma unroll
        for (int i = 0; i < 8; ++i)
#pragma unroll
            for (int j = 0; j < 4; ++j) acc[i][j] = 0ull;

        for (int c0 = 0; c0 < 8; c0++) {
            __syncthreads();
            // stage zsT[32 c][128 rows] (stride 132) from z, coalesced
            {
                const float* src = z + (((size_t)(bb * CDIM + c0 * 32 + zr)) << 10)
                                     + hw0 + zf4;
                float* dst = &sm.a.zsT[zr * 132 + zf4];
#pragma unroll
                for (int s = 0; s < 4; s++)
                    *reinterpret_cast<float4*>(dst + 32 * s) =
                        *reinterpret_cast<const float4*>(src + 32 * s);
            }
            // stage es tile (16KB dense memcpy from packed e)
            {
                const unsigned long long* src =
                    g_epack + ((size_t)(kt * 8 + c0)) * 2048 + t;
#pragma unroll
                for (int s = 0; s < 8; s++) sm.a.es[t + 256 * s] = src[256 * s];
            }
            __syncthreads();

#pragma unroll 2
            for (int cc = 0; cc < 32; cc++) {
                float4 za = *reinterpret_cast<const float4*>(
                    &sm.a.zsT[cc * 132 + ty * 8]);
                float4 zb = *reinterpret_cast<const float4*>(
                    &sm.a.zsT[cc * 132 + ty * 8 + 4]);
                ulonglong2 ea = *reinterpret_cast<const ulonglong2*>(
                    &sm.a.es[cc * 64 + tx * 2]);            // pairs 2tx, 2tx+1
                ulonglong2 eb = *reinterpret_cast<const ulonglong2*>(
                    &sm.a.es[cc * 64 + 32 + tx * 2]);       // pairs 32+2tx, +1
                float zv[8] = { za.x, za.y, za.z, za.w, zb.x, zb.y, zb.z, zb.w };
#pragma unroll
                for (int i = 0; i < 8; i++) {
                    unsigned long long zz = dup2(zv[i]);
                    acc[i][0] = ffma2(zz, ea.x, acc[i][0]);
                    acc[i][1] = ffma2(zz, ea.y, acc[i][1]);
                    acc[i][2] = ffma2(zz, eb.x, acc[i][2]);
                    acc[i][3] = ffma2(zz, eb.y, acc[i][3]);
                }
            }
        }

        // tile epilogue: per-thread codes ascend over (j, half); strict < = first-min
        const int kb = kt * 128;
#pragma unroll
        for (int i = 0; i < 8; i++) {
            float zq = s_zsq[ty * 8 + i];
#pragma unroll
            for (int j = 0; j < 4; j++) {
                int pr = (j < 2) ? (2 * tx + j) : (32 + 2 * tx + (j - 2));
                int k0 = kb + 2 * pr;
                float lo, hi;
                unpack2(acc[i][j], lo, hi);
                float d0 = fmaf(-2.0f, lo, zq + s_esq[k0]);
                if (d0 < bestD[i]) { bestD[i] = d0; bestI[i] = k0; }
                float d1 = fmaf(-2.0f, hi, zq + s_esq[k0 + 1]);
                if (d1 < bestD[i]) { bestD[i] = d1; bestI[i] = k0 + 1; }
            }
        }
    }

    // cross-thread (tx) reduction per row, lowest-index tie-break
    __syncthreads();
#pragma unroll
    for (int i = 0; i < 8; ++i) {
        sm.b.d[ty * 8 + i][tx] = bestD[i];
        sm.b.i[ty * 8 + i][tx] = bestI[i];
    }
    __syncthreads();
    if (t < 128) {
        float bd = sm.b.d[t][0];
        int   bi = sm.b.i[t][0];
#pragma unroll
        for (int x = 1; x < 16; ++x) {
            float dd = sm.b.d[t][x];
            int   ii = sm.b.i[t][x];
            if (dd < bd || (dd == bd && ii < bi)) { bd = dd; bi = ii; }
        }
        g_idx[row0 + t] = bi;
    }
}

// ---------------------------------------------------------------------------
// K3: gather z_q -> out ([B,C,H,W]), per-block loss partials
// ---------------------------------------------------------------------------
__global__ void __launch_bounds__(256)
k_output(const float* __restrict__ z, const float* __restrict__ emb,
         float* __restrict__ out) {
    __shared__ float es[32][257];
    __shared__ int   sid[32];
    __shared__ float red[256];

    const int t  = threadIdx.x;
    const int n0 = blockIdx.x * 32;
    if (t < 32) sid[t] = g_idx[n0 + t];
    __syncthreads();

    const int w = t >> 5, lane = t & 31;
#pragma unroll
    for (int r = w * 4; r < w * 4 + 4; ++r) {
        const float* src = emb + (size_t)sid[r] * CDIM;
#pragma unroll
        for (int i = 0; i < CDIM; i += 32) es[r][i + lane] = src[i + lane];
    }
    __syncthreads();

    const int b = n0 >> 10, hwb = n0 & 1023;
    float acc = 0.f;
#pragma unroll 4
    for (int p = 0; p < 32; ++p) {
        int c = p * 8 + (t >> 5);
        int r = t & 31;
        size_t g = (((size_t)(b * CDIM + c)) << 10) + hwb + r;
        float v  = es[r][c];
        float zv = z[g];
        out[g] = v;
        float df = v - zv;
        acc = fmaf(df, df, acc);
    }
    red[t] = acc;
    __syncthreads();
#pragma unroll
    for (int s = 128; s; s >>= 1) {
        if (t < s) red[t] += red[t + s];
        __syncthreads();
    }
    if (!t) g_partials[blockIdx.x] = red[0];
}

// K4: final loss = (1 + BETA) * mean((z_q - z)^2)
__global__ void k_loss(float* __restrict__ lossOut) {
    __shared__ float red[256];
    const int t = threadIdx.x;
    float s = 0.f;
    for (int i = t; i < 2048; i += 256) s += g_partials[i];
    red[t] = s;
    __syncthreads();
#pragma unroll
    for (int st = 128; st; st >>= 1) {
        if (t < st) red[t] += red[t + st];
        __syncthreads();
    }
    if (!t) {
        float m = red[0] * (1.0f / 16777216.0f);
        lossOut[0] = m + 0.25f * m;
    }
}

// ---------------------------------------------------------------------------
extern "C" void kernel_launch(void* const* d_in, const int* in_sizes, int n_in,
                              void* d_out, int out_size) {
    const float* z   = (const float*)d_in[0];
    const float* emb = (const float*)d_in[1];
    float* out       = (float*)d_out;

    k_epack<<<1024, 256>>>(emb);
    k_esq<<<(KCODES * 32) / 256, 256>>>(emb);
    k_zsq<<<NROWS / 256, 256>>>(z);
    k_dist_argmin<<<NROWS / 128, 256>>>(z);
    k_output<<<NROWS / 32, 256>>>(z, emb, out);
    k_loss<<<1, 256>>>(out + (size_t)out_size - 1);
}